// round 16
// baseline (speedup 1.0000x reference)
#include <cuda_runtime.h>
#include <cuda_fp16.h>
#include <math.h>

#define TT 64
#define DM 16
#define DFF 32
#define EPSF 1e-5f

typedef unsigned long long u64;
typedef unsigned int u32;

__device__ __forceinline__ u32 h2(float hi, float lo) {
    u32 r; asm("cvt.rn.f16x2.f32 %0, %1, %2;" : "=r"(r) : "f"(hi), "f"(lo)); return r;
}
__device__ __forceinline__ u32 movm(u32 a) {
    u32 d; asm("movmatrix.sync.aligned.m8n8.trans.b16 %0, %1;" : "=r"(d) : "r"(a));
    return d;
}
__device__ __forceinline__ void mma16816(float& c0, float& c1, float& c2, float& c3,
                                         u32 a0, u32 a1, u32 a2, u32 a3,
                                         u32 b0, u32 b1)
{
    asm volatile("mma.sync.aligned.m16n8k16.row.col.f32.f16.f16.f32 "
                 "{%0,%1,%2,%3}, {%4,%5,%6,%7}, {%8,%9}, {%0,%1,%2,%3};"
                 : "+f"(c0), "+f"(c1), "+f"(c2), "+f"(c3)
                 : "r"(a0), "r"(a1), "r"(a2), "r"(a3), "r"(b0), "r"(b1));
}

__device__ __forceinline__ float gelu_f(float xv) {
    float t = xv * xv;
    float u = fmaf(t, -0.07135481627f, -1.59576912161f);
    float e = __expf(xv * u);
    return __fdividef(xv, 1.0f + e);
}
__device__ __forceinline__ float qsum(float v) {   // quad (qd) reduction
    v += __shfl_xor_sync(0xffffffff, v, 1);
    v += __shfl_xor_sync(0xffffffff, v, 2);
    return v;
}
// build one m16n8k16 B-fragment entry for this lane from a row-major [K x N] weight
__device__ __forceinline__ uint2 mk_frag(const float* __restrict__ W, int stride,
                                         int j, int qd, float sc)
{
    uint2 fr;
    fr.x = h2(sc * __ldg(W + (2 * qd + 1) * stride + j),
              sc * __ldg(W + (2 * qd    ) * stride + j));
    fr.y = h2(sc * __ldg(W + (2 * qd + 9) * stride + j),
              sc * __ldg(W + (2 * qd + 8) * stride + j));
    return fr;
}
__device__ __forceinline__ float2 ldp(const float* __restrict__ p) {
    return __ldg(reinterpret_cast<const float2*>(p));
}

__global__ __launch_bounds__(128, 4)
void block_kernel(const float* __restrict__ x, float* __restrict__ out,
                  const float* __restrict__ Wk, const float* __restrict__ Wq,
                  const float* __restrict__ Wv,
                  const float* __restrict__ g1, const float* __restrict__ B1,
                  const float* __restrict__ g2, const float* __restrict__ B2,
                  const float* __restrict__ W1, const float* __restrict__ b1,
                  const float* __restrict__ W2, const float* __restrict__ b2)
{
    const int tid = threadIdx.x;
    const int w   = tid >> 5;
    const int t   = tid & 31;
    const int g   = t >> 2;
    const int qd  = t & 3;
    const int c2  = 2 * qd;
    const long long base = (long long)blockIdx.x * 8 + w * 2;   // 2 elems/warp

    // ---- in-kernel fragment tables (L1/L2-hot broadcast reads) ----
    uint2 fq0 = mk_frag(Wq, DM, g,     qd, 0.25f);
    uint2 fq1 = mk_frag(Wq, DM, 8 + g, qd, 0.25f);
    uint2 fk0 = mk_frag(Wk, DM, g,     qd, 1.0f);
    uint2 fk1 = mk_frag(Wk, DM, 8 + g, qd, 1.0f);
    uint2 fv0 = mk_frag(Wv, DM, g,     qd, 1.0f);
    uint2 fv1 = mk_frag(Wv, DM, 8 + g, qd, 1.0f);
    uint2 w1f[4];
    #pragma unroll
    for (int nt = 0; nt < 4; nt++)
        w1f[nt] = mk_frag(W1, DFF, nt * 8 + g, qd, 1.0f);
    uint2 w2f[2][2];
    #pragma unroll
    for (int ks = 0; ks < 2; ks++)
        #pragma unroll
        for (int nt = 0; nt < 2; nt++)
            w2f[ks][nt] = mk_frag(W2 + ks * 16 * DM, DM, nt * 8 + g, qd, 1.0f);

    // ---- per-lane LN/bias params ----
    float2 g1a = ldp(g1 + c2), g1b = ldp(g1 + 8 + c2);
    float2 n1a = ldp(B1 + c2), n1b = ldp(B1 + 8 + c2);
    float2 g2a = ldp(g2 + c2), g2b = ldp(g2 + 8 + c2);
    float2 n2a = ldp(B2 + c2), n2b = ldp(B2 + 8 + c2);
    float2 b2a = ldp(b2 + c2), b2b = ldp(b2 + 8 + c2);
    float2 b1v[4];
    #pragma unroll
    for (int nt = 0; nt < 4; nt++)
        b1v[nt] = ldp(b1 + nt * 8 + c2);

    #pragma unroll 1
    for (int e = 0; e < 2; e++) {
        const float* xb = x + (base + e) * TT * DM;
        float* ob = out + (base + e) * TT * DM;

        // ---- phase 1+2: load x in fragment layout, LN1 in-frag, QKV proj ----
        u32 qa[4][4], kb0[8], kb1[8], vb0[4][2], vb1[4][2];
        #pragma unroll
        for (int m = 0; m < 4; m++) {
            const float* p0 = xb + (m * 16 + g) * DM + c2;
            float2 x00 = *reinterpret_cast<const float2*>(p0);
            float2 x01 = *reinterpret_cast<const float2*>(p0 + 8);
            float2 x10 = *reinterpret_cast<const float2*>(p0 + 8 * DM);
            float2 x11 = *reinterpret_cast<const float2*>(p0 + 8 * DM + 8);

            float mu0 = qsum(x00.x + x00.y + x01.x + x01.y) * (1.0f / DM);
            float mu1 = qsum(x10.x + x10.y + x11.x + x11.y) * (1.0f / DM);
            float d, v0 = 0.f, v1 = 0.f;
            d = x00.x - mu0; v0 += d * d;  d = x00.y - mu0; v0 += d * d;
            d = x01.x - mu0; v0 += d * d;  d = x01.y - mu0; v0 += d * d;
            d = x10.x - mu1; v1 += d * d;  d = x10.y - mu1; v1 += d * d;
            d = x11.x - mu1; v1 += d * d;  d = x11.y - mu1; v1 += d * d;
            float r0s = rsqrtf(qsum(v0) * (1.0f / DM) + EPSF);
            float r1s = rsqrtf(qsum(v1) * (1.0f / DM) + EPSF);

            u32 a0 = h2((x00.y - mu0) * r0s * g1a.y + n1a.y,
                        (x00.x - mu0) * r0s * g1a.x + n1a.x);
            u32 a1 = h2((x10.y - mu1) * r1s * g1a.y + n1a.y,
                        (x10.x - mu1) * r1s * g1a.x + n1a.x);
            u32 a2 = h2((x01.y - mu0) * r0s * g1b.y + n1b.y,
                        (x01.x - mu0) * r0s * g1b.x + n1b.x);
            u32 a3 = h2((x11.y - mu1) * r1s * g1b.y + n1b.y,
                        (x11.x - mu1) * r1s * g1b.x + n1b.x);

            {   // Q -> A-frags
                float c0=0,c1=0,cc2=0,c3=0, d0=0,d1=0,d2=0,d3=0;
                mma16816(c0,c1,cc2,c3, a0,a1,a2,a3, fq0.x,fq0.y);
                mma16816(d0,d1,d2,d3, a0,a1,a2,a3, fq1.x,fq1.y);
                qa[m][0] = h2(c1, c0);
                qa[m][1] = h2(c3, cc2);
                qa[m][2] = h2(d1, d0);
                qa[m][3] = h2(d3, d2);
            }
            {   // K -> B-frags
                float c0=0,c1=0,cc2=0,c3=0, d0=0,d1=0,d2=0,d3=0;
                mma16816(c0,c1,cc2,c3, a0,a1,a2,a3, fk0.x,fk0.y);
                mma16816(d0,d1,d2,d3, a0,a1,a2,a3, fk1.x,fk1.y);
                kb0[2*m]     = h2(c1, c0);
                kb0[2*m + 1] = h2(c3, cc2);
                kb1[2*m]     = h2(d1, d0);
                kb1[2*m + 1] = h2(d3, d2);
            }
            {   // V -> transposed B-frags via movmatrix
                float c0=0,c1=0,cc2=0,c3=0, d0=0,d1=0,d2=0,d3=0;
                mma16816(c0,c1,cc2,c3, a0,a1,a2,a3, fv0.x,fv0.y);
                mma16816(d0,d1,d2,d3, a0,a1,a2,a3, fv1.x,fv1.y);
                vb0[m][0] = movm(h2(c1, c0));
                vb1[m][0] = movm(h2(c3, cc2));
                vb0[m][1] = movm(h2(d1, d0));
                vb1[m][1] = movm(h2(d3, d2));
            }
        }

        // ---- phase 3-5 fused per m-tile (two-phase softmax for ILP) ----
        #pragma unroll
        for (int m = 0; m < 4; m++) {
            const int r0 = m * 16 + g, r1 = r0 + 8;
            float ee[8][4];
            float l0 = 0.f, l1 = 0.f;
            #pragma unroll
            for (int j = 0; j < 8; j++) {
                if (j > 2 * m + 1) continue;
                float c0 = 0.f, c1 = 0.f, cc2 = 0.f, c3 = 0.f;
                mma16816(c0, c1, cc2, c3, qa[m][0], qa[m][1], qa[m][2], qa[m][3],
                         kb0[j], kb1[j]);
                int col = j * 8 + c2;
                ee[j][0] = (col     <= r0) ? __expf(c0) : 0.f;
                ee[j][1] = (col + 1 <= r0) ? __expf(c1) : 0.f;
                ee[j][2] = (col     <= r1) ? __expf(cc2) : 0.f;
                ee[j][3] = (col + 1 <= r1) ? __expf(c3) : 0.f;
                l0 += ee[j][0] + ee[j][1];
                l1 += ee[j][2] + ee[j][3];
            }
            l0 = qsum(l0); l1 = qsum(l1);
            float inv0 = __fdividef(1.0f, l0), inv1 = __fdividef(1.0f, l1);

            u32 pa[4][4];
            #pragma unroll
            for (int s = 0; s < 4; s++) {
                if (s > m) continue;
                pa[s][0] = h2(ee[2 * s][1],     ee[2 * s][0]);
                pa[s][1] = h2(ee[2 * s][3],     ee[2 * s][2]);
                pa[s][2] = h2(ee[2 * s + 1][1], ee[2 * s + 1][0]);
                pa[s][3] = h2(ee[2 * s + 1][3], ee[2 * s + 1][2]);
            }

            // y via MMA, fuse residual with x re-read from global (L2-hot)
            float xn[2][4];
            #pragma unroll
            for (int nt = 0; nt < 2; nt++) {
                float y0 = 0.f, y1 = 0.f, y2 = 0.f, y3 = 0.f;
                #pragma unroll
                for (int s = 0; s < 4; s++) {
                    if (s > m) continue;
                    mma16816(y0, y1, y2, y3,
                             pa[s][0], pa[s][1], pa[s][2], pa[s][3],
                             vb0[s][nt], vb1[s][nt]);
                }
                const float* p0 = xb + r0 * DM + nt * 8 + c2;
                float2 xl0 = *reinterpret_cast<const float2*>(p0);
                float2 xl1 = *reinterpret_cast<const float2*>(p0 + 8 * DM);
                xn[nt][0] = fmaf(y0, inv0, xl0.x);
                xn[nt][1] = fmaf(y1, inv0, xl0.y);
                xn[nt][2] = fmaf(y2, inv1, xl1.x);
                xn[nt][3] = fmaf(y3, inv1, xl1.y);
            }

            // LN2 in-frag
            float mu0 = qsum(xn[0][0] + xn[0][1] + xn[1][0] + xn[1][1]) * (1.0f / DM);
            float mu1 = qsum(xn[0][2] + xn[0][3] + xn[1][2] + xn[1][3]) * (1.0f / DM);
            float d, v0 = 0.f, v1 = 0.f;
            d = xn[0][0] - mu0; v0 += d * d;  d = xn[0][1] - mu0; v0 += d * d;
            d = xn[1][0] - mu0; v0 += d * d;  d = xn[1][1] - mu0; v0 += d * d;
            d = xn[0][2] - mu1; v1 += d * d;  d = xn[0][3] - mu1; v1 += d * d;
            d = xn[1][2] - mu1; v1 += d * d;  d = xn[1][3] - mu1; v1 += d * d;
            float r0s = rsqrtf(qsum(v0) * (1.0f / DM) + EPSF);
            float r1s = rsqrtf(qsum(v1) * (1.0f / DM) + EPSF);

            u32 a0 = h2((xn[0][1] - mu0) * r0s * g2a.y + n2a.y,
                        (xn[0][0] - mu0) * r0s * g2a.x + n2a.x);
            u32 a1 = h2((xn[0][3] - mu1) * r1s * g2a.y + n2a.y,
                        (xn[0][2] - mu1) * r1s * g2a.x + n2a.x);
            u32 a2 = h2((xn[1][1] - mu0) * r0s * g2b.y + n2b.y,
                        (xn[1][0] - mu0) * r0s * g2b.x + n2b.x);
            u32 a3 = h2((xn[1][3] - mu1) * r1s * g2b.y + n2b.y,
                        (xn[1][2] - mu1) * r1s * g2b.x + n2b.x);

            // FFN1 -> GELU -> FFN2 A-frags
            float gl[4][4];
            #pragma unroll
            for (int nt = 0; nt < 4; nt++) {
                float c0 = b1v[nt].x, c1 = b1v[nt].y, cc2 = b1v[nt].x, c3 = b1v[nt].y;
                mma16816(c0, c1, cc2, c3, a0, a1, a2, a3, w1f[nt].x, w1f[nt].y);
                gl[nt][0] = gelu_f(c0); gl[nt][1] = gelu_f(c1);
                gl[nt][2] = gelu_f(cc2); gl[nt][3] = gelu_f(c3);
            }
            u32 p00 = h2(gl[0][1], gl[0][0]), p01 = h2(gl[0][3], gl[0][2]);
            u32 p02 = h2(gl[1][1], gl[1][0]), p03 = h2(gl[1][3], gl[1][2]);
            u32 p10 = h2(gl[2][1], gl[2][0]), p11 = h2(gl[2][3], gl[2][2]);
            u32 p12 = h2(gl[3][1], gl[3][0]), p13 = h2(gl[3][3], gl[3][2]);

            // FFN2 + residual, store straight out
            #pragma unroll
            for (int nt = 0; nt < 2; nt++) {
                float2 bb = nt ? b2b : b2a;
                float c0 = xn[nt][0] + bb.x, c1 = xn[nt][1] + bb.y;
                float cc2 = xn[nt][2] + bb.x, c3 = xn[nt][3] + bb.y;
                mma16816(c0, c1, cc2, c3, p00, p01, p02, p03, w2f[0][nt].x, w2f[0][nt].y);
                mma16816(c0, c1, cc2, c3, p10, p11, p12, p13, w2f[1][nt].x, w2f[1][nt].y);
                float* o0 = ob + r0 * DM + nt * 8 + c2;
                *reinterpret_cast<float2*>(o0)          = make_float2(c0, c1);
                *reinterpret_cast<float2*>(o0 + 8 * DM) = make_float2(cc2, c3);
            }
        }
    }
}

extern "C" void kernel_launch(void* const* d_in, const int* in_sizes, int n_in,
                              void* d_out, int out_size)
{
    const float* x = (const float*)d_in[0];
    float* out = (float*)d_out;

    int B = in_sizes[0] / (TT * DM);
    dim3 grid(B / 8);                    // 2 elems/warp x 4 warps = 8 per CTA
    block_kernel<<<grid, 128>>>(x, out,
                                (const float*)d_in[1], (const float*)d_in[2],
                                (const float*)d_in[3], (const float*)d_in[4],
                                (const float*)d_in[5], (const float*)d_in[6],
                                (const float*)d_in[7], (const float*)d_in[8],
                                (const float*)d_in[9], (const float*)d_in[10],
                                (const float*)d_in[11]);
}

// round 17
// speedup vs baseline: 1.4110x; 1.4110x over previous
#include <cuda_runtime.h>
#include <cuda_fp16.h>
#include <math.h>

#define TT 64
#define DM 16
#define DFF 32
#define EPSF 1e-5f

// flat parameter bank offsets (floats)
#define OFF_B1  0
#define OFF_B2  32
#define OFF_G1  48
#define OFF_BE1 64
#define OFF_G2  80
#define OFF_BE2 96
#define NPARAM  112

__device__ __align__(16) float gPf[NPARAM];

typedef unsigned long long u64;
typedef unsigned int u32;

// Precomputed fp16 B-fragments (m16n8k16 layout), per-lane tables
__device__ __align__(16) uint2 gFK[2][32];
__device__ __align__(16) uint2 gFQ[2][32];        // x0.25 folded
__device__ __align__(16) uint2 gFV[2][32];
__device__ __align__(16) uint2 gFW1[4][32];
__device__ __align__(16) uint2 gFW2[2][2][32];

__device__ __forceinline__ float2 ldp2(int off) {   // 8B param load, L1-broadcast
    return __ldg(reinterpret_cast<const float2*>(&gPf[off]));
}
__device__ __forceinline__ u32 h2(float hi, float lo) {
    u32 r; asm("cvt.rn.f16x2.f32 %0, %1, %2;" : "=r"(r) : "f"(hi), "f"(lo)); return r;
}
__device__ __forceinline__ u32 movm(u32 a) {
    u32 d; asm("movmatrix.sync.aligned.m8n8.trans.b16 %0, %1;" : "=r"(d) : "r"(a));
    return d;
}
__device__ __forceinline__ void mma16816(float& c0, float& c1, float& c2, float& c3,
                                         u32 a0, u32 a1, u32 a2, u32 a3,
                                         u32 b0, u32 b1)
{
    asm volatile("mma.sync.aligned.m16n8k16.row.col.f32.f16.f16.f32 "
                 "{%0,%1,%2,%3}, {%4,%5,%6,%7}, {%8,%9}, {%0,%1,%2,%3};"
                 : "+f"(c0), "+f"(c1), "+f"(c2), "+f"(c3)
                 : "r"(a0), "r"(a1), "r"(a2), "r"(a3), "r"(b0), "r"(b1));
}

__device__ __forceinline__ float gelu_f(float xv) {
    float t = xv * xv;
    float u = fmaf(t, -0.07135481627f, -1.59576912161f);
    float e = __expf(xv * u);
    return __fdividef(xv, 1.0f + e);
}
__device__ __forceinline__ float qsum(float v) {   // quad (qd) reduction
    v += __shfl_xor_sync(0xffffffff, v, 1);
    v += __shfl_xor_sync(0xffffffff, v, 2);
    return v;
}

// ---- pack kernel: scalar params + fp16 B-fragment tables ----
__global__ void pack_kernel(const float* Wk, const float* Wq, const float* Wv,
                            const float* g1, const float* B1,
                            const float* g2, const float* B2,
                            const float* W1, const float* b1,
                            const float* W2, const float* b2)
{
    int i = threadIdx.x;
    if (i < DFF) gPf[OFF_B1 + i] = b1[i];
    if (i < DM) {
        gPf[OFF_B2 + i]  = b2[i];
        gPf[OFF_G1 + i]  = g1[i];  gPf[OFF_BE1 + i] = B1[i];
        gPf[OFF_G2 + i]  = g2[i];  gPf[OFF_BE2 + i] = B2[i];
    }

    int lane = i & 31;
    int qd = lane & 3, g = lane >> 2;
    if (i < 192) {
        int wsel = i >> 6, nt = (i >> 5) & 1;
        const float* W = (wsel == 0) ? Wk : (wsel == 1) ? Wq : Wv;
        float sc = (wsel == 1) ? 0.25f : 1.0f;
        int j = nt * 8 + g;
        uint2 fr;
        fr.x = h2(sc * W[(2*qd+1)*DM + j], sc * W[(2*qd  )*DM + j]);
        fr.y = h2(sc * W[(2*qd+9)*DM + j], sc * W[(2*qd+8)*DM + j]);
        if (wsel == 0) gFK[nt][lane] = fr;
        else if (wsel == 1) gFQ[nt][lane] = fr;
        else gFV[nt][lane] = fr;
    }
    if (i < 128) {
        int nt = i >> 5;
        int j = nt * 8 + g;
        uint2 fr;
        fr.x = h2(W1[(2*qd+1)*DFF + j], W1[(2*qd  )*DFF + j]);
        fr.y = h2(W1[(2*qd+9)*DFF + j], W1[(2*qd+8)*DFF + j]);
        gFW1[nt][lane] = fr;
    }
    if (i < 128) {
        int ks = i >> 6, nt = (i >> 5) & 1;
        int j = nt * 8 + g;
        int kb = ks * 16;
        uint2 fr;
        fr.x = h2(W2[(kb+2*qd+1)*DM + j], W2[(kb+2*qd  )*DM + j]);
        fr.y = h2(W2[(kb+2*qd+9)*DM + j], W2[(kb+2*qd+8)*DM + j]);
        gFW2[ks][nt][lane] = fr;
    }
}

__global__ __launch_bounds__(128, 4)
void block_kernel(const float* __restrict__ x, float* __restrict__ out)
{
    const int tid = threadIdx.x;
    const int w   = tid >> 5;
    const int t   = tid & 31;
    const int g   = t >> 2;
    const int qd  = t & 3;
    const int c2  = 2 * qd;
    const long long base = (long long)blockIdx.x * 8 + w * 2;   // 2 elems/warp

    // ---- hoisted per-lane params + weight fragment tables (amortized) ----
    float2 g1a = ldp2(OFF_G1 + c2),  g1b = ldp2(OFF_G1 + 8 + c2);
    float2 n1a = ldp2(OFF_BE1 + c2), n1b = ldp2(OFF_BE1 + 8 + c2);
    float2 g2a = ldp2(OFF_G2 + c2),  g2b = ldp2(OFF_G2 + 8 + c2);
    float2 n2a = ldp2(OFF_BE2 + c2), n2b = ldp2(OFF_BE2 + 8 + c2);
    float2 b2a = ldp2(OFF_B2 + c2),  b2b = ldp2(OFF_B2 + 8 + c2);
    float2 b1v[4];
    #pragma unroll
    for (int nt = 0; nt < 4; nt++)
        b1v[nt] = ldp2(OFF_B1 + nt * 8 + c2);
    uint2 fq0 = gFQ[0][t], fq1 = gFQ[1][t];
    uint2 fk0 = gFK[0][t], fk1 = gFK[1][t];
    uint2 fv0 = gFV[0][t], fv1 = gFV[1][t];
    uint2 w1f[4] = { gFW1[0][t], gFW1[1][t], gFW1[2][t], gFW1[3][t] };
    uint2 w2f[2][2] = { { gFW2[0][0][t], gFW2[0][1][t] },
                        { gFW2[1][0][t], gFW2[1][1][t] } };

    #pragma unroll 1
    for (int e = 0; e < 2; e++) {
        const float* xb = x + (base + e) * TT * DM;
        float* ob = out + (base + e) * TT * DM;

        // ---- phase 1+2: load x in fragment layout, LN1 in-frag, QKV proj ----
        u32 qa[4][4], kb0[8], kb1[8], vb0[4][2], vb1[4][2];
        #pragma unroll
        for (int m = 0; m < 4; m++) {
            const float* p0 = xb + (m * 16 + g) * DM + c2;
            float2 x00 = *reinterpret_cast<const float2*>(p0);
            float2 x01 = *reinterpret_cast<const float2*>(p0 + 8);
            float2 x10 = *reinterpret_cast<const float2*>(p0 + 8 * DM);
            float2 x11 = *reinterpret_cast<const float2*>(p0 + 8 * DM + 8);

            float mu0 = qsum(x00.x + x00.y + x01.x + x01.y) * (1.0f / DM);
            float mu1 = qsum(x10.x + x10.y + x11.x + x11.y) * (1.0f / DM);
            float d, v0 = 0.f, v1 = 0.f;
            d = x00.x - mu0; v0 += d * d;  d = x00.y - mu0; v0 += d * d;
            d = x01.x - mu0; v0 += d * d;  d = x01.y - mu0; v0 += d * d;
            d = x10.x - mu1; v1 += d * d;  d = x10.y - mu1; v1 += d * d;
            d = x11.x - mu1; v1 += d * d;  d = x11.y - mu1; v1 += d * d;
            float r0s = rsqrtf(qsum(v0) * (1.0f / DM) + EPSF);
            float r1s = rsqrtf(qsum(v1) * (1.0f / DM) + EPSF);

            u32 a0 = h2((x00.y - mu0) * r0s * g1a.y + n1a.y,
                        (x00.x - mu0) * r0s * g1a.x + n1a.x);
            u32 a1 = h2((x10.y - mu1) * r1s * g1a.y + n1a.y,
                        (x10.x - mu1) * r1s * g1a.x + n1a.x);
            u32 a2 = h2((x01.y - mu0) * r0s * g1b.y + n1b.y,
                        (x01.x - mu0) * r0s * g1b.x + n1b.x);
            u32 a3 = h2((x11.y - mu1) * r1s * g1b.y + n1b.y,
                        (x11.x - mu1) * r1s * g1b.x + n1b.x);

            {   // Q -> A-frags
                float c0=0,c1=0,cc2=0,c3=0, d0=0,d1=0,d2=0,d3=0;
                mma16816(c0,c1,cc2,c3, a0,a1,a2,a3, fq0.x,fq0.y);
                mma16816(d0,d1,d2,d3, a0,a1,a2,a3, fq1.x,fq1.y);
                qa[m][0] = h2(c1, c0);
                qa[m][1] = h2(c3, cc2);
                qa[m][2] = h2(d1, d0);
                qa[m][3] = h2(d3, d2);
            }
            {   // K -> B-frags
                float c0=0,c1=0,cc2=0,c3=0, d0=0,d1=0,d2=0,d3=0;
                mma16816(c0,c1,cc2,c3, a0,a1,a2,a3, fk0.x,fk0.y);
                mma16816(d0,d1,d2,d3, a0,a1,a2,a3, fk1.x,fk1.y);
                kb0[2*m]     = h2(c1, c0);
                kb0[2*m + 1] = h2(c3, cc2);
                kb1[2*m]     = h2(d1, d0);
                kb1[2*m + 1] = h2(d3, d2);
            }
            {   // V -> transposed B-frags via movmatrix
                float c0=0,c1=0,cc2=0,c3=0, d0=0,d1=0,d2=0,d3=0;
                mma16816(c0,c1,cc2,c3, a0,a1,a2,a3, fv0.x,fv0.y);
                mma16816(d0,d1,d2,d3, a0,a1,a2,a3, fv1.x,fv1.y);
                vb0[m][0] = movm(h2(c1, c0));
                vb1[m][0] = movm(h2(c3, cc2));
                vb0[m][1] = movm(h2(d1, d0));
                vb1[m][1] = movm(h2(d3, d2));
            }
        }

        // ---- phase 3-5 fused per m-tile (two-phase softmax for ILP) ----
        #pragma unroll
        for (int m = 0; m < 4; m++) {
            const int r0 = m * 16 + g, r1 = r0 + 8;
            float ee[8][4];
            float l0 = 0.f, l1 = 0.f;
            #pragma unroll
            for (int j = 0; j < 8; j++) {
                if (j > 2 * m + 1) continue;
                float c0 = 0.f, c1 = 0.f, cc2 = 0.f, c3 = 0.f;
                mma16816(c0, c1, cc2, c3, qa[m][0], qa[m][1], qa[m][2], qa[m][3],
                         kb0[j], kb1[j]);
                int col = j * 8 + c2;
                ee[j][0] = (col     <= r0) ? __expf(c0) : 0.f;
                ee[j][1] = (col + 1 <= r0) ? __expf(c1) : 0.f;
                ee[j][2] = (col     <= r1) ? __expf(cc2) : 0.f;
                ee[j][3] = (col + 1 <= r1) ? __expf(c3) : 0.f;
                l0 += ee[j][0] + ee[j][1];
                l1 += ee[j][2] + ee[j][3];
            }
            l0 = qsum(l0); l1 = qsum(l1);
            float inv0 = __fdividef(1.0f, l0), inv1 = __fdividef(1.0f, l1);

            u32 pa[4][4];
            #pragma unroll
            for (int s = 0; s < 4; s++) {
                if (s > m) continue;
                pa[s][0] = h2(ee[2 * s][1],     ee[2 * s][0]);
                pa[s][1] = h2(ee[2 * s][3],     ee[2 * s][2]);
                pa[s][2] = h2(ee[2 * s + 1][1], ee[2 * s + 1][0]);
                pa[s][3] = h2(ee[2 * s + 1][3], ee[2 * s + 1][2]);
            }

            // y via MMA, fuse residual with x re-read from global (L2-hot)
            float xn[2][4];
            #pragma unroll
            for (int nt = 0; nt < 2; nt++) {
                float y0 = 0.f, y1 = 0.f, y2 = 0.f, y3 = 0.f;
                #pragma unroll
                for (int s = 0; s < 4; s++) {
                    if (s > m) continue;
                    mma16816(y0, y1, y2, y3,
                             pa[s][0], pa[s][1], pa[s][2], pa[s][3],
                             vb0[s][nt], vb1[s][nt]);
                }
                const float* p0 = xb + r0 * DM + nt * 8 + c2;
                float2 xl0 = *reinterpret_cast<const float2*>(p0);
                float2 xl1 = *reinterpret_cast<const float2*>(p0 + 8 * DM);
                xn[nt][0] = fmaf(y0, inv0, xl0.x);
                xn[nt][1] = fmaf(y1, inv0, xl0.y);
                xn[nt][2] = fmaf(y2, inv1, xl1.x);
                xn[nt][3] = fmaf(y3, inv1, xl1.y);
            }

            // LN2 in-frag
            float mu0 = qsum(xn[0][0] + xn[0][1] + xn[1][0] + xn[1][1]) * (1.0f / DM);
            float mu1 = qsum(xn[0][2] + xn[0][3] + xn[1][2] + xn[1][3]) * (1.0f / DM);
            float d, v0 = 0.f, v1 = 0.f;
            d = xn[0][0] - mu0; v0 += d * d;  d = xn[0][1] - mu0; v0 += d * d;
            d = xn[1][0] - mu0; v0 += d * d;  d = xn[1][1] - mu0; v0 += d * d;
            d = xn[0][2] - mu1; v1 += d * d;  d = xn[0][3] - mu1; v1 += d * d;
            d = xn[1][2] - mu1; v1 += d * d;  d = xn[1][3] - mu1; v1 += d * d;
            float r0s = rsqrtf(qsum(v0) * (1.0f / DM) + EPSF);
            float r1s = rsqrtf(qsum(v1) * (1.0f / DM) + EPSF);

            u32 a0 = h2((xn[0][1] - mu0) * r0s * g2a.y + n2a.y,
                        (xn[0][0] - mu0) * r0s * g2a.x + n2a.x);
            u32 a1 = h2((xn[0][3] - mu1) * r1s * g2a.y + n2a.y,
                        (xn[0][2] - mu1) * r1s * g2a.x + n2a.x);
            u32 a2 = h2((xn[1][1] - mu0) * r0s * g2b.y + n2b.y,
                        (xn[1][0] - mu0) * r0s * g2b.x + n2b.x);
            u32 a3 = h2((xn[1][3] - mu1) * r1s * g2b.y + n2b.y,
                        (xn[1][2] - mu1) * r1s * g2b.x + n2b.x);

            // FFN1 -> GELU -> FFN2 A-frags
            float gl[4][4];
            #pragma unroll
            for (int nt = 0; nt < 4; nt++) {
                float c0 = b1v[nt].x, c1 = b1v[nt].y, cc2 = b1v[nt].x, c3 = b1v[nt].y;
                mma16816(c0, c1, cc2, c3, a0, a1, a2, a3, w1f[nt].x, w1f[nt].y);
                gl[nt][0] = gelu_f(c0); gl[nt][1] = gelu_f(c1);
                gl[nt][2] = gelu_f(cc2); gl[nt][3] = gelu_f(c3);
            }
            u32 p00 = h2(gl[0][1], gl[0][0]), p01 = h2(gl[0][3], gl[0][2]);
            u32 p02 = h2(gl[1][1], gl[1][0]), p03 = h2(gl[1][3], gl[1][2]);
            u32 p10 = h2(gl[2][1], gl[2][0]), p11 = h2(gl[2][3], gl[2][2]);
            u32 p12 = h2(gl[3][1], gl[3][0]), p13 = h2(gl[3][3], gl[3][2]);

            // FFN2 + residual, store straight out
            #pragma unroll
            for (int nt = 0; nt < 2; nt++) {
                float2 bb = nt ? b2b : b2a;
                float c0 = xn[nt][0] + bb.x, c1 = xn[nt][1] + bb.y;
                float cc2 = xn[nt][2] + bb.x, c3 = xn[nt][3] + bb.y;
                mma16816(c0, c1, cc2, c3, p00, p01, p02, p03, w2f[0][nt].x, w2f[0][nt].y);
                mma16816(c0, c1, cc2, c3, p10, p11, p12, p13, w2f[1][nt].x, w2f[1][nt].y);
                float* o0 = ob + r0 * DM + nt * 8 + c2;
                *reinterpret_cast<float2*>(o0)          = make_float2(c0, c1);
                *reinterpret_cast<float2*>(o0 + 8 * DM) = make_float2(cc2, c3);
            }
        }
    }
}

extern "C" void kernel_launch(void* const* d_in, const int* in_sizes, int n_in,
                              void* d_out, int out_size)
{
    const float* x = (const float*)d_in[0];
    float* out = (float*)d_out;

    pack_kernel<<<1, 256>>>((const float*)d_in[1], (const float*)d_in[2],
                            (const float*)d_in[3], (const float*)d_in[4],
                            (const float*)d_in[5], (const float*)d_in[6],
                            (const float*)d_in[7], (const float*)d_in[8],
                            (const float*)d_in[9], (const float*)d_in[10],
                            (const float*)d_in[11]);

    int B = in_sizes[0] / (TT * DM);
    dim3 grid(B / 8);                    // 2 elems/warp x 4 warps = 8 per CTA
    block_kernel<<<grid, 128>>>(x, out);
}